// round 14
// baseline (speedup 1.0000x reference)
#include <cuda_runtime.h>
#include <cuda_fp16.h>
#include <math.h>
#include <stdint.h>

// Problem constants
constexpr int B  = 2;
constexpr int S  = 2048;
constexpr int D  = 1024;
constexpr int H  = 16;
constexpr int HD = 64;
constexpr int M  = B * S;          // 4096
constexpr int BH = B * H;          // 32

// ---------------------------------------------------------------------------
// Device scratch
// ---------------------------------------------------------------------------
__device__ __half g_xh[M * D];           // fp16 x
__device__ __half g_wth[4 * D * D];      // transposed fp16 weights WT[n][k] (q,k,v,o)
__device__ __half g_qh[BH * S * HD];     // fp16 Q (pre-scaled by log2e/8), [b,h,s,hd]
__device__ __half g_kh[BH * S * HD];     // fp16 K
__device__ __half g_vh[BH * S * HD];     // fp16 V
__device__ __half g_ah[M * D];           // attention out fp16, [b,s,d]

// ---------------------------------------------------------------------------
// Helpers
// ---------------------------------------------------------------------------
__device__ __forceinline__ uint32_t h2_as_u32(__half2 h) {
    union { __half2 h; uint32_t u; } cvt;
    cvt.h = h;
    return cvt.u;
}

__device__ __forceinline__ uint32_t h2exp2_u32(uint32_t d) {
    uint32_t r;
    asm("ex2.approx.f16x2 %0, %1;" : "=r"(r) : "r"(d));
    return r;
}

__device__ __forceinline__ void mma_f16(float c[4], uint32_t a0, uint32_t a1,
                                        uint32_t a2, uint32_t a3,
                                        uint32_t b0, uint32_t b1) {
    asm volatile(
        "mma.sync.aligned.m16n8k16.row.col.f32.f16.f16.f32 "
        "{%0,%1,%2,%3}, {%4,%5,%6,%7}, {%8,%9}, {%0,%1,%2,%3};"
        : "+f"(c[0]), "+f"(c[1]), "+f"(c[2]), "+f"(c[3])
        : "r"(a0), "r"(a1), "r"(a2), "r"(a3), "r"(b0), "r"(b1));
}

__device__ __forceinline__ void ldsm4(uint32_t& r0, uint32_t& r1,
                                      uint32_t& r2, uint32_t& r3, uint32_t saddr) {
    asm volatile("ldmatrix.sync.aligned.m8n8.x4.shared.b16 {%0,%1,%2,%3}, [%4];"
        : "=r"(r0), "=r"(r1), "=r"(r2), "=r"(r3) : "r"(saddr));
}

__device__ __forceinline__ void ldsm4t(uint32_t& r0, uint32_t& r1,
                                       uint32_t& r2, uint32_t& r3, uint32_t saddr) {
    asm volatile("ldmatrix.sync.aligned.m8n8.x4.trans.shared.b16 {%0,%1,%2,%3}, [%4];"
        : "=r"(r0), "=r"(r1), "=r"(r2), "=r"(r3) : "r"(saddr));
}

__device__ __forceinline__ uint32_t smem_u32(const void* p) {
    return (uint32_t)__cvta_generic_to_shared(p);
}

__device__ __forceinline__ void cp16(uint32_t dst, const void* src) {
    asm volatile("cp.async.cg.shared.global [%0], [%1], 16;" :: "r"(dst), "l"(src));
}
#define CP_COMMIT() asm volatile("cp.async.commit_group;" ::: "memory")
#define CP_WAIT1()  asm volatile("cp.async.wait_group 1;" ::: "memory")

// ---------------------------------------------------------------------------
// x -> fp16
// ---------------------------------------------------------------------------
__global__ __launch_bounds__(256)
void f2h_kernel(const float* __restrict__ in, __half* __restrict__ out, int n4)
{
    int i = blockIdx.x * blockDim.x + threadIdx.x;
    if (i < n4) {
        float4 v = ((const float4*)in)[i];
        __half2 lo = __floats2half2_rn(v.x, v.y);
        __half2 hi = __floats2half2_rn(v.z, v.w);
        ((uint2*)out)[i] = make_uint2(h2_as_u32(lo), h2_as_u32(hi));
    }
}

// ---------------------------------------------------------------------------
// Weight transpose + fp16: WT[n][k] = h(W[k][n]), 4 matrices (grid.z)
// ---------------------------------------------------------------------------
__global__ __launch_bounds__(256)
void transpose_kernel(const float* __restrict__ W0, const float* __restrict__ W1,
                      const float* __restrict__ W2, const float* __restrict__ W3,
                      __half* __restrict__ out)
{
    __shared__ float t[32][33];
    const float* Ws[4] = {W0, W1, W2, W3};
    const float* W = Ws[blockIdx.z];
    __half* O = out + (size_t)blockIdx.z * D * D;

    const int x = blockIdx.x * 32 + threadIdx.x;
    const int y0 = blockIdx.y * 32;
#pragma unroll
    for (int i = 0; i < 4; i++)
        t[threadIdx.y + i * 8][threadIdx.x] = W[(size_t)(y0 + threadIdx.y + i * 8) * D + x];
    __syncthreads();
    const int xo = y0 + threadIdx.x;
#pragma unroll
    for (int i = 0; i < 4; i++)
        O[(size_t)(blockIdx.x * 32 + threadIdx.y + i * 8) * D + xo] =
            __float2half_rn(t[threadIdx.x][threadIdx.y + i * 8]);
}

// ---------------------------------------------------------------------------
// Big-tile fp16 GEMM, cp.async 3-stage pipeline, KC=64 (16 barriers total).
// CTA 256x128, 512 threads = 16 warps (4x4 grid, warp tile 64x32).
// smem pitch 72 halves (144B) - ldmatrix conflict-free.
// ---------------------------------------------------------------------------
constexpr int GPITCH  = 72;                   // halves per smem row (144 B)
constexpr int KC      = 64;
constexpr int GST     = 3;
constexpr int ASTG_H  = 256 * GPITCH;         // 18432 halves
constexpr int BSTG_H  = 128 * GPITCH;         // 9216 halves
constexpr int GSMEM   = (GST * (ASTG_H + BSTG_H)) * 2 + 512;   // 166400 B

struct GemmP {
    const float* bias[4];
    void*        out[4];
    float        scale[4];
    int          headmajor;
};

__global__ __launch_bounds__(512, 1)
void gemm_big(const __half* __restrict__ A, const __half* __restrict__ WT, GemmP p)
{
    extern __shared__ __half sm[];
    __half* As = sm;
    __half* Bs = sm + GST * ASTG_H;
    float*  bsm = (float*)(sm + GST * (ASTG_H + BSTG_H));

    const int tid = threadIdx.x, lane = tid & 31, warp = tid >> 5;
    const int m0 = blockIdx.y * 256;
    const int ng0 = blockIdx.x * 128;
    const int mat = ng0 >> 10;
    const int n0l = ng0 & 1023;
    const int wm = (warp >> 2) * 64;
    const int wn = (warp & 3) * 32;

    if (tid < 128) bsm[tid] = p.bias[mat][n0l + tid];

    const __half* Ag = A  + (size_t)m0 * 1024;
    const __half* Bg = WT + (size_t)ng0 * 1024;

    const uint32_t asb = smem_u32(As);
    const uint32_t bsb = smem_u32(Bs);

    // Loaders (512 threads), KC=64:
    // A: 256 rows x 64 halves; thread t -> row t>>1, 32-half chunk (t&1)*32 (4 cp16)
    // B: 128 rows x 64 halves; thread t -> row t>>2, 16-half chunk (t&3)*16 (2 cp16)
    const int arow_ld = tid >> 1, ach_ld = (tid & 1) * 32;
    const int brow_ld = tid >> 2, bch_ld = (tid & 3) * 16;

    auto issue_stage = [&](int stg, int k0) {
        const uint32_t ad = asb + (stg * ASTG_H + arow_ld * GPITCH + ach_ld) * 2;
        const __half* as = &Ag[(size_t)arow_ld * 1024 + k0 + ach_ld];
#pragma unroll
        for (int j = 0; j < 4; j++)
            cp16(ad + j * 16, as + j * 8);
        const uint32_t bd = bsb + (stg * BSTG_H + brow_ld * GPITCH + bch_ld) * 2;
        const __half* bs = &Bg[(size_t)brow_ld * 1024 + k0 + bch_ld];
#pragma unroll
        for (int j = 0; j < 2; j++)
            cp16(bd + j * 16, bs + j * 8);
    };

    issue_stage(0, 0);  CP_COMMIT();
    issue_stage(1, KC); CP_COMMIT();

    uint32_t arow[4], brow[2];
#pragma unroll
    for (int mt = 0; mt < 4; mt++)
        arow[mt] = (wm + mt * 16 + (lane & 15)) * GPITCH + (lane >> 4) * 8;
#pragma unroll
    for (int pp = 0; pp < 2; pp++)
        brow[pp] = (wn + pp * 16 + (lane & 15)) * GPITCH + (lane >> 4) * 8;

    float c[4][4][4];
#pragma unroll
    for (int mt = 0; mt < 4; mt++)
#pragma unroll
        for (int nt = 0; nt < 4; nt++)
#pragma unroll
            for (int i = 0; i < 4; i++) c[mt][nt][i] = 0.f;

    int cur = 0;
    for (int step = 0; step < 1024 / KC; step++) {
        CP_WAIT1();
        __syncthreads();

        const uint32_t ab = asb + cur * ASTG_H * 2;
        const uint32_t bb = bsb + cur * BSTG_H * 2;
#pragma unroll
        for (int koff = 0; koff < KC; koff += 16) {
            uint32_t af[4][4], bf[4][2];
#pragma unroll
            for (int mt = 0; mt < 4; mt++)
                ldsm4(af[mt][0], af[mt][1], af[mt][2], af[mt][3],
                      ab + (arow[mt] + koff) * 2);
#pragma unroll
            for (int pp = 0; pp < 2; pp++) {
                uint32_t r0, r1, r2, r3;
                ldsm4(r0, r1, r2, r3, bb + (brow[pp] + koff) * 2);
                bf[2 * pp][0] = r0; bf[2 * pp + 1][0] = r1;
                bf[2 * pp][1] = r2; bf[2 * pp + 1][1] = r3;
            }
#pragma unroll
            for (int mt = 0; mt < 4; mt++)
#pragma unroll
                for (int nt = 0; nt < 4; nt++)
                    mma_f16(c[mt][nt], af[mt][0], af[mt][1], af[mt][2], af[mt][3],
                            bf[nt][0], bf[nt][1]);
        }
        if (step + 2 < 1024 / KC) {
            int nst = cur + 2; if (nst >= GST) nst -= GST;
            issue_stage(nst, (step + 2) * KC);
        }
        CP_COMMIT();
        if (++cur == GST) cur = 0;
    }

    const float osc = p.scale[mat];
#pragma unroll
    for (int mt = 0; mt < 4; mt++) {
        const int r0 = m0 + wm + mt * 16 + (lane >> 2);
#pragma unroll
        for (int nt = 0; nt < 4; nt++) {
            const int nl = wn + nt * 8 + 2 * (lane & 3);
            const int n = n0l + nl;
            const float v0 = (c[mt][nt][0] + bsm[nl])     * osc;
            const float v1 = (c[mt][nt][1] + bsm[nl + 1]) * osc;
            const float v2 = (c[mt][nt][2] + bsm[nl])     * osc;
            const float v3 = (c[mt][nt][3] + bsm[nl + 1]) * osc;
            if (p.headmajor) {
                __half* O = (__half*)p.out[mat];
                const int h = n >> 6, hd = n & 63;
                const int b0_ = r0 >> 11, s0_ = r0 & (S - 1);
                const int b1_ = (r0 + 8) >> 11, s1_ = (r0 + 8) & (S - 1);
                *(__half2*)&O[((size_t)(b0_ * H + h) * S + s0_) * 64 + hd] =
                    __floats2half2_rn(v0, v1);
                *(__half2*)&O[((size_t)(b1_ * H + h) * S + s1_) * 64 + hd] =
                    __floats2half2_rn(v2, v3);
            } else {
                float* O = (float*)p.out[mat];
                *(float2*)&O[(size_t)r0 * 1024 + n]       = make_float2(v0, v1);
                *(float2*)&O[(size_t)(r0 + 8) * 1024 + n] = make_float2(v2, v3);
            }
        }
    }
}

// ---------------------------------------------------------------------------
// fp16 flash attention (unchanged from R13): 128 q/CTA, 256 thr, 3-stage
// cp.async, ldmatrix, log2-domain max-free softmax, ones-column row sums.
// ---------------------------------------------------------------------------
constexpr int AST    = 3;
constexpr int APITCH = 72;
constexpr int TSTG   = 64 * APITCH;
constexpr int QROWS  = 128;
constexpr int ASMEM  = (QROWS * APITCH + 2 * AST * TSTG) * 2;   // 73728 B
constexpr uint32_t ONES_H2 = 0x3C003C00u;

__global__ __launch_bounds__(256, 2)
void attn_mma(const __half* __restrict__ Q, const __half* __restrict__ K,
              const __half* __restrict__ V, __half* __restrict__ Out)
{
    extern __shared__ __half asm_[];
    __half* Qs = asm_;
    __half* Ks = asm_ + QROWS * APITCH;
    __half* Vs = Ks + AST * TSTG;

    const int tid = threadIdx.x, lane = tid & 31, warp = tid >> 5;
    const int bh = blockIdx.y, q0 = blockIdx.x * QROWS;
    const __half* Qg = Q + ((size_t)bh * S + q0) * 64;
    const __half* Kg = K + (size_t)bh * S * 64;
    const __half* Vg = V + (size_t)bh * S * 64;

    const uint32_t qsb = smem_u32(Qs);
    const uint32_t ksb = smem_u32(Ks);
    const uint32_t vsb = smem_u32(Vs);

    const int krow = tid >> 2, kch = (tid & 3) * 16;
    auto issue_kv = [&](int stg, int kb) {
        const uint32_t kd = ksb + (stg * TSTG + krow * APITCH + kch) * 2;
        const __half* ks = &Kg[(size_t)(kb + krow) * 64 + kch];
        cp16(kd, ks);
        cp16(kd + 16, ks + 8);
        const uint32_t vd = vsb + (stg * TSTG + krow * APITCH + kch) * 2;
        const __half* vs = &Vg[(size_t)(kb + krow) * 64 + kch];
        cp16(vd, vs);
        cp16(vd + 16, vs + 8);
    };

    issue_kv(0, 0);  CP_COMMIT();
    issue_kv(1, 64); CP_COMMIT();

#pragma unroll
    for (int i = 0; i < 4; i++) {
        const int slot = tid + i * 256, row = slot >> 3, c8 = slot & 7;
        *(uint4*)&Qs[row * APITCH + c8 * 8] = *(const uint4*)&Qg[(size_t)row * 64 + c8 * 8];
    }
    __syncthreads();

    uint32_t qa[4][4];
#pragma unroll
    for (int kk = 0; kk < 4; kk++)
        ldsm4(qa[kk][0], qa[kk][1], qa[kk][2], qa[kk][3],
              qsb + ((warp * 16 + (lane & 15)) * APITCH + kk * 16 + (lane >> 4) * 8) * 2);

    uint32_t koffs[4];
#pragma unroll
    for (int g = 0; g < 4; g++)
        koffs[g] = (g * 16 + (lane & 15)) * APITCH + (lane >> 4) * 8;
    const int vrow_in = ((lane >> 3) & 1) * 8 + (lane & 7);
    const int vcol_in = (lane >> 4) * 8;

    float o[8][4];
#pragma unroll
    for (int dt = 0; dt < 8; dt++)
#pragma unroll
        for (int i = 0; i < 4; i++) o[dt][i] = 0.f;
    float ol[4] = {0.f, 0.f, 0.f, 0.f};

    int cur = 0;
    for (int kt = 0; kt < 32; kt++) {
        CP_WAIT1();
        __syncthreads();
        if (kt + 2 < 32) {
            int nst = cur + 2; if (nst >= AST) nst -= AST;
            issue_kv(nst, (kt + 2) * 64);
        }
        CP_COMMIT();

        const uint32_t kb = ksb + cur * TSTG * 2;
        const uint32_t vb = vsb + cur * TSTG * 2;

        float sc[8][4];
#pragma unroll
        for (int nt = 0; nt < 8; nt++)
#pragma unroll
            for (int i = 0; i < 4; i++) sc[nt][i] = 0.f;
#pragma unroll
        for (int kk = 0; kk < 4; kk++) {
            uint32_t bf[8][2];
#pragma unroll
            for (int g = 0; g < 4; g++) {
                uint32_t r0, r1, r2, r3;
                ldsm4(r0, r1, r2, r3, kb + (koffs[g] + kk * 16) * 2);
                bf[2 * g][0] = r0; bf[2 * g + 1][0] = r1;
                bf[2 * g][1] = r2; bf[2 * g + 1][1] = r3;
            }
#pragma unroll
            for (int nt = 0; nt < 8; nt++)
                mma_f16(sc[nt], qa[kk][0], qa[kk][1], qa[kk][2], qa[kk][3],
                        bf[nt][0], bf[nt][1]);
        }

        uint32_t ph[8][2];
#pragma unroll
        for (int nt = 0; nt < 8; nt++) {
            ph[nt][0] = h2exp2_u32(h2_as_u32(__floats2half2_rn(sc[nt][0], sc[nt][1])));
            ph[nt][1] = h2exp2_u32(h2_as_u32(__floats2half2_rn(sc[nt][2], sc[nt][3])));
        }

#pragma unroll
        for (int kk = 0; kk < 4; kk++) {
            uint32_t bv[8][2];
#pragma unroll
            for (int dg = 0; dg < 4; dg++) {
                uint32_t r0, r1, r2, r3;
                ldsm4t(r0, r1, r2, r3,
                       vb + ((kk * 16 + vrow_in) * APITCH + dg * 16 + vcol_in) * 2);
                bv[2 * dg][0] = r0; bv[2 * dg][1] = r1;
                bv[2 * dg + 1][0] = r2; bv[2 * dg + 1][1] = r3;
            }
#pragma unroll
            for (int dt = 0; dt < 8; dt++)
                mma_f16(o[dt], ph[2 * kk][0], ph[2 * kk][1],
                        ph[2 * kk + 1][0], ph[2 * kk + 1][1],
                        bv[dt][0], bv[dt][1]);
            mma_f16(ol, ph[2 * kk][0], ph[2 * kk][1],
                    ph[2 * kk + 1][0], ph[2 * kk + 1][1],
                    ONES_H2, ONES_H2);
        }

        if (++cur == AST) cur = 0;
    }

    const float i0 = 1.f / ol[0], i1 = 1.f / ol[2];
    const int b = bh >> 4, h = bh & 15;
    const int gr0 = q0 + warp * 16 + (lane >> 2);
    __half* Ob0 = Out + ((size_t)(b * S + gr0)) * 1024 + h * 64;
    __half* Ob1 = Ob0 + (size_t)8 * 1024;
#pragma unroll
    for (int dt = 0; dt < 8; dt++) {
        const int col = dt * 8 + 2 * (lane & 3);
        *(__half2*)&Ob0[col] = __floats2half2_rn(o[dt][0] * i0, o[dt][1] * i0);
        *(__half2*)&Ob1[col] = __floats2half2_rn(o[dt][2] * i1, o[dt][3] * i1);
    }
}

// ---------------------------------------------------------------------------
// Launch
// ---------------------------------------------------------------------------
extern "C" void kernel_launch(void* const* d_in, const int* in_sizes, int n_in,
                              void* d_out, int out_size)
{
    (void)in_sizes; (void)n_in; (void)out_size;

    const float* x  = (const float*)d_in[0];
    const float* Wq = (const float*)d_in[1];
    const float* bq = (const float*)d_in[2];
    const float* Wk = (const float*)d_in[3];
    const float* bk = (const float*)d_in[4];
    const float* Wv = (const float*)d_in[5];
    const float* bv = (const float*)d_in[6];
    const float* Wo = (const float*)d_in[7];
    const float* bo = (const float*)d_in[8];
    float* out = (float*)d_out;

    __half *xh, *wt, *qp, *kp, *vp, *ah;
    cudaGetSymbolAddress((void**)&xh, g_xh);
    cudaGetSymbolAddress((void**)&wt, g_wth);
    cudaGetSymbolAddress((void**)&qp, g_qh);
    cudaGetSymbolAddress((void**)&kp, g_kh);
    cudaGetSymbolAddress((void**)&vp, g_vh);
    cudaGetSymbolAddress((void**)&ah, g_ah);

    cudaFuncSetAttribute(gemm_big, cudaFuncAttributeMaxDynamicSharedMemorySize, GSMEM);
    cudaFuncSetAttribute(attn_mma, cudaFuncAttributeMaxDynamicSharedMemorySize, ASMEM);

    // Prep: x -> fp16, transpose+convert weights
    f2h_kernel<<<(M * D / 4 + 255) / 256, 256>>>(x, xh, M * D / 4);
    transpose_kernel<<<dim3(32, 32, 4), dim3(32, 8)>>>(Wq, Wk, Wv, Wo, wt);

    // Fused QKV projection. Q pre-scale folds 1/sqrt(HD) and log2(e).
    GemmP pq;
    pq.bias[0] = bq; pq.bias[1] = bk; pq.bias[2] = bv; pq.bias[3] = bo;
    pq.out[0] = qp;  pq.out[1] = kp;  pq.out[2] = vp;  pq.out[3] = nullptr;
    pq.scale[0] = 0.125f * 1.4426950408889634f;
    pq.scale[1] = 1.f; pq.scale[2] = 1.f; pq.scale[3] = 1.f;
    pq.headmajor = 1;
    gemm_big<<<dim3(24, M / 256), 512, GSMEM>>>(xh, wt, pq);

    // Attention: 128 queries per CTA
    attn_mma<<<dim3(S / QROWS, BH), 256, ASMEM>>>(qp, kp, vp, ah);

    // Output projection (fp32 out)
    GemmP po;
    po.bias[0] = bo; po.bias[1] = bo; po.bias[2] = bo; po.bias[3] = bo;
    po.out[0] = out; po.out[1] = out; po.out[2] = out; po.out[3] = out;
    po.scale[0] = 1.f; po.scale[1] = 1.f; po.scale[2] = 1.f; po.scale[3] = 1.f;
    po.headmajor = 0;
    gemm_big<<<dim3(8, M / 256), 512, GSMEM>>>(ah, wt + 3 * D * D, po);
}

// round 15
// speedup vs baseline: 1.0410x; 1.0410x over previous
#include <cuda_runtime.h>
#include <cuda_fp16.h>
#include <math.h>
#include <stdint.h>

// Problem constants
constexpr int B  = 2;
constexpr int S  = 2048;
constexpr int D  = 1024;
constexpr int H  = 16;
constexpr int HD = 64;
constexpr int M  = B * S;          // 4096
constexpr int BH = B * H;          // 32

// ---------------------------------------------------------------------------
// Device scratch
// ---------------------------------------------------------------------------
__device__ __half g_xh[M * D];           // fp16 x
__device__ __half g_wth[4 * D * D];      // transposed fp16 weights WT[n][k] (q,k,v,o)
__device__ __half g_qh[BH * S * HD];     // fp16 Q (pre-scaled by log2e/8), [b,h,s,hd]
__device__ __half g_kh[BH * S * HD];     // fp16 K
__device__ __half g_vh[BH * S * HD];     // fp16 V
__device__ __half g_ah[M * D];           // attention out fp16, [b,s,d]

// ---------------------------------------------------------------------------
// Helpers
// ---------------------------------------------------------------------------
__device__ __forceinline__ uint32_t h2_as_u32(__half2 h) {
    union { __half2 h; uint32_t u; } cvt;
    cvt.h = h;
    return cvt.u;
}

__device__ __forceinline__ uint32_t h2exp2_u32(uint32_t d) {
    uint32_t r;
    asm("ex2.approx.f16x2 %0, %1;" : "=r"(r) : "r"(d));
    return r;
}

__device__ __forceinline__ void mma_f16(float c[4], uint32_t a0, uint32_t a1,
                                        uint32_t a2, uint32_t a3,
                                        uint32_t b0, uint32_t b1) {
    asm volatile(
        "mma.sync.aligned.m16n8k16.row.col.f32.f16.f16.f32 "
        "{%0,%1,%2,%3}, {%4,%5,%6,%7}, {%8,%9}, {%0,%1,%2,%3};"
        : "+f"(c[0]), "+f"(c[1]), "+f"(c[2]), "+f"(c[3])
        : "r"(a0), "r"(a1), "r"(a2), "r"(a3), "r"(b0), "r"(b1));
}

__device__ __forceinline__ void ldsm4(uint32_t& r0, uint32_t& r1,
                                      uint32_t& r2, uint32_t& r3, uint32_t saddr) {
    asm volatile("ldmatrix.sync.aligned.m8n8.x4.shared.b16 {%0,%1,%2,%3}, [%4];"
        : "=r"(r0), "=r"(r1), "=r"(r2), "=r"(r3) : "r"(saddr));
}

__device__ __forceinline__ void ldsm4t(uint32_t& r0, uint32_t& r1,
                                       uint32_t& r2, uint32_t& r3, uint32_t saddr) {
    asm volatile("ldmatrix.sync.aligned.m8n8.x4.trans.shared.b16 {%0,%1,%2,%3}, [%4];"
        : "=r"(r0), "=r"(r1), "=r"(r2), "=r"(r3) : "r"(saddr));
}

__device__ __forceinline__ uint32_t smem_u32(const void* p) {
    return (uint32_t)__cvta_generic_to_shared(p);
}

__device__ __forceinline__ void cp16(uint32_t dst, const void* src) {
    asm volatile("cp.async.cg.shared.global [%0], [%1], 16;" :: "r"(dst), "l"(src));
}
#define CP_COMMIT() asm volatile("cp.async.commit_group;" ::: "memory")
#define CP_WAIT2()  asm volatile("cp.async.wait_group 2;" ::: "memory")
#define CP_WAIT1()  asm volatile("cp.async.wait_group 1;" ::: "memory")

// ---------------------------------------------------------------------------
// x -> fp16
// ---------------------------------------------------------------------------
__global__ __launch_bounds__(256)
void f2h_kernel(const float* __restrict__ in, __half* __restrict__ out, int n4)
{
    int i = blockIdx.x * blockDim.x + threadIdx.x;
    if (i < n4) {
        float4 v = ((const float4*)in)[i];
        __half2 lo = __floats2half2_rn(v.x, v.y);
        __half2 hi = __floats2half2_rn(v.z, v.w);
        ((uint2*)out)[i] = make_uint2(h2_as_u32(lo), h2_as_u32(hi));
    }
}

// ---------------------------------------------------------------------------
// Weight transpose + fp16: WT[n][k] = h(W[k][n]), 4 matrices (grid.z)
// ---------------------------------------------------------------------------
__global__ __launch_bounds__(256)
void transpose_kernel(const float* __restrict__ W0, const float* __restrict__ W1,
                      const float* __restrict__ W2, const float* __restrict__ W3,
                      __half* __restrict__ out)
{
    __shared__ float t[32][33];
    const float* Ws[4] = {W0, W1, W2, W3};
    const float* W = Ws[blockIdx.z];
    __half* O = out + (size_t)blockIdx.z * D * D;

    const int x = blockIdx.x * 32 + threadIdx.x;
    const int y0 = blockIdx.y * 32;
#pragma unroll
    for (int i = 0; i < 4; i++)
        t[threadIdx.y + i * 8][threadIdx.x] = W[(size_t)(y0 + threadIdx.y + i * 8) * D + x];
    __syncthreads();
    const int xo = y0 + threadIdx.x;
#pragma unroll
    for (int i = 0; i < 4; i++)
        O[(size_t)(blockIdx.x * 32 + threadIdx.y + i * 8) * D + xo] =
            __float2half_rn(t[threadIdx.x][threadIdx.y + i * 8]);
}

// ---------------------------------------------------------------------------
// Big-tile fp16 GEMM, cp.async 4-stage pipeline (R12/R13 proven config).
// CTA 256x128, 512 threads = 16 warps (4x4 grid, warp tile 64x32).
// ---------------------------------------------------------------------------
constexpr int PITCH   = 40;                   // halves per smem row (80 B)
constexpr int KC      = 32;
constexpr int STAGES  = 4;
constexpr int ASTG_H  = 256 * PITCH;
constexpr int BSTG_H  = 128 * PITCH;
constexpr int GSMEM   = (STAGES * (ASTG_H + BSTG_H)) * 2 + 512;

struct GemmP {
    const float* bias[4];
    void*        out[4];
    float        scale[4];
    int          headmajor;
};

__global__ __launch_bounds__(512, 1)
void gemm_big(const __half* __restrict__ A, const __half* __restrict__ WT, GemmP p)
{
    extern __shared__ __half sm[];
    __half* As = sm;
    __half* Bs = sm + STAGES * ASTG_H;
    float*  bsm = (float*)(sm + STAGES * (ASTG_H + BSTG_H));

    const int tid = threadIdx.x, lane = tid & 31, warp = tid >> 5;
    const int m0 = blockIdx.y * 256;
    const int ng0 = blockIdx.x * 128;
    const int mat = ng0 >> 10;
    const int n0l = ng0 & 1023;
    const int wm = (warp >> 2) * 64;
    const int wn = (warp & 3) * 32;

    if (tid < 128) bsm[tid] = p.bias[mat][n0l + tid];

    const __half* Ag = A  + (size_t)m0 * 1024;
    const __half* Bg = WT + (size_t)ng0 * 1024;

    const uint32_t asb = smem_u32(As);
    const uint32_t bsb = smem_u32(Bs);

    const int arow_ld = tid >> 1, ach_ld = (tid & 1) * 16;
    const int brow_ld = tid >> 2, bch_ld = (tid & 3) * 8;

    auto issue_stage = [&](int stg, int k0) {
        const uint32_t ad = asb + (stg * ASTG_H + arow_ld * PITCH + ach_ld) * 2;
        const __half* as = &Ag[(size_t)arow_ld * 1024 + k0 + ach_ld];
        cp16(ad, as);
        cp16(ad + 16, as + 8);
        const uint32_t bd = bsb + (stg * BSTG_H + brow_ld * PITCH + bch_ld) * 2;
        cp16(bd, &Bg[(size_t)brow_ld * 1024 + k0 + bch_ld]);
    };

#pragma unroll
    for (int s = 0; s < STAGES - 1; s++) {
        issue_stage(s, s * KC);
        CP_COMMIT();
    }

    uint32_t arow[4], brow[2];
#pragma unroll
    for (int mt = 0; mt < 4; mt++)
        arow[mt] = (wm + mt * 16 + (lane & 15)) * PITCH + (lane >> 4) * 8;
#pragma unroll
    for (int pp = 0; pp < 2; pp++)
        brow[pp] = (wn + pp * 16 + (lane & 15)) * PITCH + (lane >> 4) * 8;

    float c[4][4][4];
#pragma unroll
    for (int mt = 0; mt < 4; mt++)
#pragma unroll
        for (int nt = 0; nt < 4; nt++)
#pragma unroll
            for (int i = 0; i < 4; i++) c[mt][nt][i] = 0.f;

    for (int step = 0; step < 1024 / KC; step++) {
        const int cur = step & (STAGES - 1);
        CP_WAIT2();
        __syncthreads();

        const uint32_t ab = asb + cur * ASTG_H * 2;
        const uint32_t bb = bsb + cur * BSTG_H * 2;
#pragma unroll
        for (int koff = 0; koff < KC; koff += 16) {
            uint32_t af[4][4], bf[4][2];
#pragma unroll
            for (int mt = 0; mt < 4; mt++)
                ldsm4(af[mt][0], af[mt][1], af[mt][2], af[mt][3],
                      ab + (arow[mt] + koff) * 2);
#pragma unroll
            for (int pp = 0; pp < 2; pp++) {
                uint32_t r0, r1, r2, r3;
                ldsm4(r0, r1, r2, r3, bb + (brow[pp] + koff) * 2);
                bf[2 * pp][0] = r0; bf[2 * pp + 1][0] = r1;
                bf[2 * pp][1] = r2; bf[2 * pp + 1][1] = r3;
            }
#pragma unroll
            for (int mt = 0; mt < 4; mt++)
#pragma unroll
                for (int nt = 0; nt < 4; nt++)
                    mma_f16(c[mt][nt], af[mt][0], af[mt][1], af[mt][2], af[mt][3],
                            bf[nt][0], bf[nt][1]);
        }
        if (step + STAGES - 1 < 1024 / KC)
            issue_stage((step + STAGES - 1) & (STAGES - 1), (step + STAGES - 1) * KC);
        CP_COMMIT();
    }

    const float osc = p.scale[mat];
#pragma unroll
    for (int mt = 0; mt < 4; mt++) {
        const int r0 = m0 + wm + mt * 16 + (lane >> 2);
#pragma unroll
        for (int nt = 0; nt < 4; nt++) {
            const int nl = wn + nt * 8 + 2 * (lane & 3);
            const int n = n0l + nl;
            const float v0 = (c[mt][nt][0] + bsm[nl])     * osc;
            const float v1 = (c[mt][nt][1] + bsm[nl + 1]) * osc;
            const float v2 = (c[mt][nt][2] + bsm[nl])     * osc;
            const float v3 = (c[mt][nt][3] + bsm[nl + 1]) * osc;
            if (p.headmajor) {
                __half* O = (__half*)p.out[mat];
                const int h = n >> 6, hd = n & 63;
                const int b0_ = r0 >> 11, s0_ = r0 & (S - 1);
                const int b1_ = (r0 + 8) >> 11, s1_ = (r0 + 8) & (S - 1);
                *(__half2*)&O[((size_t)(b0_ * H + h) * S + s0_) * 64 + hd] =
                    __floats2half2_rn(v0, v1);
                *(__half2*)&O[((size_t)(b1_ * H + h) * S + s1_) * 64 + hd] =
                    __floats2half2_rn(v2, v3);
            } else {
                float* O = (float*)p.out[mat];
                *(float2*)&O[(size_t)r0 * 1024 + n]       = make_float2(v0, v1);
                *(float2*)&O[(size_t)(r0 + 8) * 1024 + n] = make_float2(v2, v3);
            }
        }
    }
}

// ---------------------------------------------------------------------------
// fp16 flash attention with deferred-PV software pipelining.
// 128 q/CTA, 256 thr (8 warps). K ring 3 stages, V ring 4 stages (V is
// consumed one tile late: PV(i-1) runs between QK(i) and exp(i), hiding
// the exp/cvt latency behind independent MMAs). Max-free log2 softmax,
// ones-column row sums.
// ---------------------------------------------------------------------------
constexpr int APITCH = 72;
constexpr int TSTG   = 64 * APITCH;       // halves per K or V stage (4608)
constexpr int KRING  = 3;
constexpr int VRING  = 4;
constexpr int QROWS  = 128;
constexpr int ASMEM  = (QROWS * APITCH + (KRING + VRING) * TSTG) * 2;  // 82944 B
constexpr uint32_t ONES_H2 = 0x3C003C00u;

__global__ __launch_bounds__(256, 2)
void attn_mma(const __half* __restrict__ Q, const __half* __restrict__ K,
              const __half* __restrict__ V, __half* __restrict__ Out)
{
    extern __shared__ __half asm_[];
    __half* Qs = asm_;
    __half* Ks = asm_ + QROWS * APITCH;
    __half* Vs = Ks + KRING * TSTG;

    const int tid = threadIdx.x, lane = tid & 31, warp = tid >> 5;
    const int bh = blockIdx.y, q0 = blockIdx.x * QROWS;
    const __half* Qg = Q + ((size_t)bh * S + q0) * 64;
    const __half* Kg = K + (size_t)bh * S * 64;
    const __half* Vg = V + (size_t)bh * S * 64;

    const uint32_t qsb = smem_u32(Qs);
    const uint32_t ksb = smem_u32(Ks);
    const uint32_t vsb = smem_u32(Vs);

    const int krow = tid >> 2, kch = (tid & 3) * 16;
    // Issues K into stage kt%3 and V into stage kt%4 for key-block kb.
    auto issue_kv = [&](int kstg, int vstg, int kb) {
        const uint32_t kd = ksb + (kstg * TSTG + krow * APITCH + kch) * 2;
        const __half* ks = &Kg[(size_t)(kb + krow) * 64 + kch];
        cp16(kd, ks);
        cp16(kd + 16, ks + 8);
        const uint32_t vd = vsb + (vstg * TSTG + krow * APITCH + kch) * 2;
        const __half* vs = &Vg[(size_t)(kb + krow) * 64 + kch];
        cp16(vd, vs);
        cp16(vd + 16, vs + 8);
    };

    issue_kv(0, 0, 0);   CP_COMMIT();
    issue_kv(1, 1, 64);  CP_COMMIT();

#pragma unroll
    for (int i = 0; i < 4; i++) {
        const int slot = tid + i * 256, row = slot >> 3, c8 = slot & 7;
        *(uint4*)&Qs[row * APITCH + c8 * 8] = *(const uint4*)&Qg[(size_t)row * 64 + c8 * 8];
    }
    __syncthreads();

    uint32_t qa[4][4];
#pragma unroll
    for (int kk = 0; kk < 4; kk++)
        ldsm4(qa[kk][0], qa[kk][1], qa[kk][2], qa[kk][3],
              qsb + ((warp * 16 + (lane & 15)) * APITCH + kk * 16 + (lane >> 4) * 8) * 2);

    uint32_t koffs[4];
#pragma unroll
    for (int g = 0; g < 4; g++)
        koffs[g] = (g * 16 + (lane & 15)) * APITCH + (lane >> 4) * 8;
    const int vrow_in = ((lane >> 3) & 1) * 8 + (lane & 7);
    const int vcol_in = (lane >> 4) * 8;

    float o[8][4];
#pragma unroll
    for (int dt = 0; dt < 8; dt++)
#pragma unroll
        for (int i = 0; i < 4; i++) o[dt][i] = 0.f;
    float ol[4] = {0.f, 0.f, 0.f, 0.f};

    uint32_t ph[8][2];   // P fragments of the PREVIOUS tile (deferred PV)

    // QK for one tile (K stage base kb), producing ph via exp2
    auto do_qk_exp = [&](uint32_t kb) {
        float sc[8][4];
#pragma unroll
        for (int nt = 0; nt < 8; nt++)
#pragma unroll
            for (int i = 0; i < 4; i++) sc[nt][i] = 0.f;
#pragma unroll
        for (int kk = 0; kk < 4; kk++) {
            uint32_t bf[8][2];
#pragma unroll
            for (int g = 0; g < 4; g++) {
                uint32_t r0, r1, r2, r3;
                ldsm4(r0, r1, r2, r3, kb + (koffs[g] + kk * 16) * 2);
                bf[2 * g][0] = r0; bf[2 * g + 1][0] = r1;
                bf[2 * g][1] = r2; bf[2 * g + 1][1] = r3;
            }
#pragma unroll
            for (int nt = 0; nt < 8; nt++)
                mma_f16(sc[nt], qa[kk][0], qa[kk][1], qa[kk][2], qa[kk][3],
                        bf[nt][0], bf[nt][1]);
        }
        return_sc:;
        // exp (log2 domain, max-free)
#pragma unroll
        for (int nt = 0; nt < 8; nt++) {
            ph[nt][0] = h2exp2_u32(h2_as_u32(__floats2half2_rn(sc[nt][0], sc[nt][1])));
            ph[nt][1] = h2exp2_u32(h2_as_u32(__floats2half2_rn(sc[nt][2], sc[nt][3])));
        }
    };

    // PV for the tile whose P is in ph (V stage base vb)
    auto do_pv = [&](uint32_t vb) {
#pragma unroll
        for (int kk = 0; kk < 4; kk++) {
            uint32_t bv[8][2];
#pragma unroll
            for (int dg = 0; dg < 4; dg++) {
                uint32_t r0, r1, r2, r3;
                ldsm4t(r0, r1, r2, r3,
                       vb + ((kk * 16 + vrow_in) * APITCH + dg * 16 + vcol_in) * 2);
                bv[2 * dg][0] = r0; bv[2 * dg][1] = r1;
                bv[2 * dg + 1][0] = r2; bv[2 * dg + 1][1] = r3;
            }
#pragma unroll
            for (int dt = 0; dt < 8; dt++)
                mma_f16(o[dt], ph[2 * kk][0], ph[2 * kk][1],
                        ph[2 * kk + 1][0], ph[2 * kk + 1][1],
                        bv[dt][0], bv[dt][1]);
            mma_f16(ol, ph[2 * kk][0], ph[2 * kk][1],
                    ph[2 * kk + 1][0], ph[2 * kk + 1][1],
                    ONES_H2, ONES_H2);
        }
    };

    // ---- Peeled tile 0: QK + exp only (no PV yet) ----
    CP_WAIT1();
    __syncthreads();
    issue_kv(2 % KRING, 2 % VRING, 2 * 64);
    CP_COMMIT();
    do_qk_exp(ksb + 0 * TSTG * 2);

    // ---- Main loop: QK(kt), PV(kt-1), exp(kt) ----
    int kc = 1, vc = 1;         // current K/V ring slots for tile kt
    int vprev = 0;              // V ring slot of tile kt-1
    int knxt = 0, vnxt = 3;     // ring slots for tile kt+2 (kt=1 -> 3%3=0, 3%4=3)
    for (int kt = 1; kt < 32; kt++) {
        CP_WAIT1();
        __syncthreads();
        if (kt + 2 < 32) issue_kv(knxt, vnxt, (kt + 2) * 64);
        CP_COMMIT();

        // QK for tile kt -> sc (inside do_qk_exp, exp at the end)
        // Interleave: QK MMAs first, then PV(kt-1) hides exp dependency.
        {
            float sc[8][4];
#pragma unroll
            for (int nt = 0; nt < 8; nt++)
#pragma unroll
                for (int i = 0; i < 4; i++) sc[nt][i] = 0.f;
            const uint32_t kb = ksb + kc * TSTG * 2;
#pragma unroll
            for (int kk = 0; kk < 4; kk++) {
                uint32_t bf[8][2];
#pragma unroll
                for (int g = 0; g < 4; g++) {
                    uint32_t r0, r1, r2, r3;
                    ldsm4(r0, r1, r2, r3, kb + (koffs[g] + kk * 16) * 2);
                    bf[2 * g][0] = r0; bf[2 * g + 1][0] = r1;
                    bf[2 * g][1] = r2; bf[2 * g + 1][1] = r3;
                }
#pragma unroll
                for (int nt = 0; nt < 8; nt++)
                    mma_f16(sc[nt], qa[kk][0], qa[kk][1], qa[kk][2], qa[kk][3],
                            bf[nt][0], bf[nt][1]);
            }

            // PV for tile kt-1 (independent of sc; hides QK latency + exp below)
            do_pv(vsb + vprev * TSTG * 2);

            // exp for tile kt -> ph (overwrites consumed values)
#pragma unroll
            for (int nt = 0; nt < 8; nt++) {
                ph[nt][0] = h2exp2_u32(h2_as_u32(__floats2half2_rn(sc[nt][0], sc[nt][1])));
                ph[nt][1] = h2exp2_u32(h2_as_u32(__floats2half2_rn(sc[nt][2], sc[nt][3])));
            }
        }

        vprev = vc;
        if (++kc == KRING) kc = 0;
        if (++vc == VRING) vc = 0;
        if (++knxt == KRING) knxt = 0;
        if (++vnxt == VRING) vnxt = 0;
    }

    // ---- Final PV for tile 31 ----
    do_pv(vsb + vprev * TSTG * 2);

    const float i0 = 1.f / ol[0], i1 = 1.f / ol[2];
    const int b = bh >> 4, h = bh & 15;
    const int gr0 = q0 + warp * 16 + (lane >> 2);
    __half* Ob0 = Out + ((size_t)(b * S + gr0)) * 1024 + h * 64;
    __half* Ob1 = Ob0 + (size_t)8 * 1024;
#pragma unroll
    for (int dt = 0; dt < 8; dt++) {
        const int col = dt * 8 + 2 * (lane & 3);
        *(__half2*)&Ob0[col] = __floats2half2_rn(o[dt][0] * i0, o[dt][1] * i0);
        *(__half2*)&Ob1[col] = __floats2half2_rn(o[dt][2] * i1, o[dt][3] * i1);
    }
}

// ---------------------------------------------------------------------------
// Launch
// ---------------------------------------------------------------------------
extern "C" void kernel_launch(void* const* d_in, const int* in_sizes, int n_in,
                              void* d_out, int out_size)
{
    (void)in_sizes; (void)n_in; (void)out_size;

    const float* x  = (const float*)d_in[0];
    const float* Wq = (const float*)d_in[1];
    const float* bq = (const float*)d_in[2];
    const float* Wk = (const float*)d_in[3];
    const float* bk = (const float*)d_in[4];
    const float* Wv = (const float*)d_in[5];
    const float* bv = (const float*)d_in[6];
    const float* Wo = (const float*)d_in[7];
    const float* bo = (const float*)d_in[8];
    float* out = (float*)d_out;

    __half *xh, *wt, *qp, *kp, *vp, *ah;
    cudaGetSymbolAddress((void**)&xh, g_xh);
    cudaGetSymbolAddress((void**)&wt, g_wth);
    cudaGetSymbolAddress((void**)&qp, g_qh);
    cudaGetSymbolAddress((void**)&kp, g_kh);
    cudaGetSymbolAddress((void**)&vp, g_vh);
    cudaGetSymbolAddress((void**)&ah, g_ah);

    cudaFuncSetAttribute(gemm_big, cudaFuncAttributeMaxDynamicSharedMemorySize, GSMEM);
    cudaFuncSetAttribute(attn_mma, cudaFuncAttributeMaxDynamicSharedMemorySize, ASMEM);

    // Prep: x -> fp16, transpose+convert weights
    f2h_kernel<<<(M * D / 4 + 255) / 256, 256>>>(x, xh, M * D / 4);
    transpose_kernel<<<dim3(32, 32, 4), dim3(32, 8)>>>(Wq, Wk, Wv, Wo, wt);

    // Fused QKV projection. Q pre-scale folds 1/sqrt(HD) and log2(e).
    GemmP pq;
    pq.bias[0] = bq; pq.bias[1] = bk; pq.bias[2] = bv; pq.bias[3] = bo;
    pq.out[0] = qp;  pq.out[1] = kp;  pq.out[2] = vp;  pq.out[3] = nullptr;
    pq.scale[0] = 0.125f * 1.4426950408889634f;
    pq.scale[1] = 1.f; pq.scale[2] = 1.f; pq.scale[3] = 1.f;
    pq.headmajor = 1;
    gemm_big<<<dim3(24, M / 256), 512, GSMEM>>>(xh, wt, pq);

    // Attention: 128 queries per CTA
    attn_mma<<<dim3(S / QROWS, BH), 256, ASMEM>>>(qp, kp, vp, ah);

    // Output projection (fp32 out)
    GemmP po;
    po.bias[0] = bo; po.bias[1] = bo; po.bias[2] = bo; po.bias[3] = bo;
    po.out[0] = out; po.out[1] = out; po.out[2] = out; po.out[3] = out;
    po.scale[0] = 1.f; po.scale[1] = 1.f; po.scale[2] = 1.f; po.scale[3] = 1.f;
    po.headmajor = 0;
    gemm_big<<<dim3(8, M / 256), 512, GSMEM>>>(ah, wt + 3 * D * D, po);
}

// round 16
// speedup vs baseline: 1.0432x; 1.0022x over previous
#include <cuda_runtime.h>
#include <cuda_fp16.h>
#include <math.h>
#include <stdint.h>

// Problem constants
constexpr int B  = 2;
constexpr int S  = 2048;
constexpr int D  = 1024;
constexpr int H  = 16;
constexpr int HD = 64;
constexpr int M  = B * S;          // 4096
constexpr int BH = B * H;          // 32

// ---------------------------------------------------------------------------
// Device scratch
// ---------------------------------------------------------------------------
__device__ __half g_xh[M * D];           // fp16 x
__device__ __half g_wth[4 * D * D];      // transposed fp16 weights WT[n][k] (q,k,v,o)
__device__ __half g_qh[BH * S * HD];     // fp16 Q (pre-scaled by log2e/8), [b,h,s,hd]
__device__ __half g_kh[BH * S * HD];     // fp16 K
__device__ __half g_vh[BH * S * HD];     // fp16 V
__device__ __half g_ah[M * D];           // attention out fp16, [b,s,d]

// ---------------------------------------------------------------------------
// Helpers
// ---------------------------------------------------------------------------
__device__ __forceinline__ uint32_t h2_as_u32(__half2 h) {
    union { __half2 h; uint32_t u; } cvt;
    cvt.h = h;
    return cvt.u;
}

__device__ __forceinline__ uint32_t h2exp2_u32(uint32_t d) {
    uint32_t r;
    asm("ex2.approx.f16x2 %0, %1;" : "=r"(r) : "r"(d));
    return r;
}

__device__ __forceinline__ void mma_f16(float c[4], uint32_t a0, uint32_t a1,
                                        uint32_t a2, uint32_t a3,
                                        uint32_t b0, uint32_t b1) {
    asm volatile(
        "mma.sync.aligned.m16n8k16.row.col.f32.f16.f16.f32 "
        "{%0,%1,%2,%3}, {%4,%5,%6,%7}, {%8,%9}, {%0,%1,%2,%3};"
        : "+f"(c[0]), "+f"(c[1]), "+f"(c[2]), "+f"(c[3])
        : "r"(a0), "r"(a1), "r"(a2), "r"(a3), "r"(b0), "r"(b1));
}

__device__ __forceinline__ void ldsm4(uint32_t& r0, uint32_t& r1,
                                      uint32_t& r2, uint32_t& r3, uint32_t saddr) {
    asm volatile("ldmatrix.sync.aligned.m8n8.x4.shared.b16 {%0,%1,%2,%3}, [%4];"
        : "=r"(r0), "=r"(r1), "=r"(r2), "=r"(r3) : "r"(saddr));
}

__device__ __forceinline__ void ldsm4t(uint32_t& r0, uint32_t& r1,
                                       uint32_t& r2, uint32_t& r3, uint32_t saddr) {
    asm volatile("ldmatrix.sync.aligned.m8n8.x4.trans.shared.b16 {%0,%1,%2,%3}, [%4];"
        : "=r"(r0), "=r"(r1), "=r"(r2), "=r"(r3) : "r"(saddr));
}

__device__ __forceinline__ uint32_t smem_u32(const void* p) {
    return (uint32_t)__cvta_generic_to_shared(p);
}

__device__ __forceinline__ void cp16(uint32_t dst, const void* src) {
    asm volatile("cp.async.cg.shared.global [%0], [%1], 16;" :: "r"(dst), "l"(src));
}
#define CP_COMMIT() asm volatile("cp.async.commit_group;" ::: "memory")
#define CP_WAIT2()  asm volatile("cp.async.wait_group 2;" ::: "memory")
#define CP_WAIT1()  asm volatile("cp.async.wait_group 1;" ::: "memory")

// ---------------------------------------------------------------------------
// x -> fp16
// ---------------------------------------------------------------------------
__global__ __launch_bounds__(256)
void f2h_kernel(const float* __restrict__ in, __half* __restrict__ out, int n4)
{
    int i = blockIdx.x * blockDim.x + threadIdx.x;
    if (i < n4) {
        float4 v = ((const float4*)in)[i];
        __half2 lo = __floats2half2_rn(v.x, v.y);
        __half2 hi = __floats2half2_rn(v.z, v.w);
        ((uint2*)out)[i] = make_uint2(h2_as_u32(lo), h2_as_u32(hi));
    }
}

// ---------------------------------------------------------------------------
// Weight transpose + fp16: WT[n][k] = h(W[k][n]), 4 matrices (grid.z)
// ---------------------------------------------------------------------------
__global__ __launch_bounds__(256)
void transpose_kernel(const float* __restrict__ W0, const float* __restrict__ W1,
                      const float* __restrict__ W2, const float* __restrict__ W3,
                      __half* __restrict__ out)
{
    __shared__ float t[32][33];
    const float* Ws[4] = {W0, W1, W2, W3};
    const float* W = Ws[blockIdx.z];
    __half* O = out + (size_t)blockIdx.z * D * D;

    const int x = blockIdx.x * 32 + threadIdx.x;
    const int y0 = blockIdx.y * 32;
#pragma unroll
    for (int i = 0; i < 4; i++)
        t[threadIdx.y + i * 8][threadIdx.x] = W[(size_t)(y0 + threadIdx.y + i * 8) * D + x];
    __syncthreads();
    const int xo = y0 + threadIdx.x;
#pragma unroll
    for (int i = 0; i < 4; i++)
        O[(size_t)(blockIdx.x * 32 + threadIdx.y + i * 8) * D + xo] =
            __float2half_rn(t[threadIdx.x][threadIdx.y + i * 8]);
}

// ---------------------------------------------------------------------------
// fp16 GEMM, cp.async 4-stage pipeline.
// CTA 128x128, 256 threads = 8 warps (2m x 4n grid, warp tile 64x32).
// 2 CTAs/SM (independent barrier domains) = 16 warps/SM.
// ---------------------------------------------------------------------------
constexpr int PITCH   = 40;                   // halves per smem row (80 B)
constexpr int KC      = 32;
constexpr int STAGES  = 4;
constexpr int ASTG_H  = 128 * PITCH;          // 5120 halves
constexpr int BSTG_H  = 128 * PITCH;          // 5120 halves
constexpr int GSMEM   = (STAGES * (ASTG_H + BSTG_H)) * 2 + 512;  // 82432 B

struct GemmP {
    const float* bias[4];
    void*        out[4];
    float        scale[4];
    int          headmajor;
};

__global__ __launch_bounds__(256, 2)
void gemm_big(const __half* __restrict__ A, const __half* __restrict__ WT, GemmP p)
{
    extern __shared__ __half sm[];
    __half* As = sm;
    __half* Bs = sm + STAGES * ASTG_H;
    float*  bsm = (float*)(sm + STAGES * (ASTG_H + BSTG_H));

    const int tid = threadIdx.x, lane = tid & 31, warp = tid >> 5;
    const int m0 = blockIdx.y * 128;
    const int ng0 = blockIdx.x * 128;
    const int mat = ng0 >> 10;
    const int n0l = ng0 & 1023;
    const int wm = (warp >> 2) * 64;          // 2 m groups of 64
    const int wn = (warp & 3) * 32;           // 4 n groups of 32

    if (tid < 128) bsm[tid] = p.bias[mat][n0l + tid];

    const __half* Ag = A  + (size_t)m0 * 1024;
    const __half* Bg = WT + (size_t)ng0 * 1024;

    const uint32_t asb = smem_u32(As);
    const uint32_t bsb = smem_u32(Bs);

    // Loaders (256 threads), KC=32:
    // A and B: 128 rows x 32 halves each; thread t -> row t>>1,
    // 16-half chunk (t&1)*16, 2 cp16 per tensor.
    const int lrow = tid >> 1, lch = (tid & 1) * 16;

    auto issue_stage = [&](int stg, int k0) {
        const uint32_t ad = asb + (stg * ASTG_H + lrow * PITCH + lch) * 2;
        const __half* as = &Ag[(size_t)lrow * 1024 + k0 + lch];
        cp16(ad, as);
        cp16(ad + 16, as + 8);
        const uint32_t bd = bsb + (stg * BSTG_H + lrow * PITCH + lch) * 2;
        const __half* bs = &Bg[(size_t)lrow * 1024 + k0 + lch];
        cp16(bd, bs);
        cp16(bd + 16, bs + 8);
    };

#pragma unroll
    for (int s = 0; s < STAGES - 1; s++) {
        issue_stage(s, s * KC);
        CP_COMMIT();
    }

    uint32_t arow[4], brow[2];
#pragma unroll
    for (int mt = 0; mt < 4; mt++)
        arow[mt] = (wm + mt * 16 + (lane & 15)) * PITCH + (lane >> 4) * 8;
#pragma unroll
    for (int pp = 0; pp < 2; pp++)
        brow[pp] = (wn + pp * 16 + (lane & 15)) * PITCH + (lane >> 4) * 8;

    float c[4][4][4];
#pragma unroll
    for (int mt = 0; mt < 4; mt++)
#pragma unroll
        for (int nt = 0; nt < 4; nt++)
#pragma unroll
            for (int i = 0; i < 4; i++) c[mt][nt][i] = 0.f;

    for (int step = 0; step < 1024 / KC; step++) {
        const int cur = step & (STAGES - 1);
        CP_WAIT2();
        __syncthreads();

        const uint32_t ab = asb + cur * ASTG_H * 2;
        const uint32_t bb = bsb + cur * BSTG_H * 2;
#pragma unroll
        for (int koff = 0; koff < KC; koff += 16) {
            uint32_t af[4][4], bf[4][2];
            // A fragments: wm..wm+63 = 4 x m16 tiles (rows wm+mt*16)
#pragma unroll
            for (int mt = 0; mt < 4; mt++) {
                const int r = (wm + (mt & 1) * 16 + (mt >> 1) * 32);
                // keep simple: recompute from arow (arow built for mt*16)
            }
#pragma unroll
            for (int mt = 0; mt < 4; mt++)
                ldsm4(af[mt][0], af[mt][1], af[mt][2], af[mt][3],
                      ab + (arow[mt] + koff) * 2);
#pragma unroll
            for (int pp = 0; pp < 2; pp++) {
                uint32_t r0, r1, r2, r3;
                ldsm4(r0, r1, r2, r3, bb + (brow[pp] + koff) * 2);
                bf[2 * pp][0] = r0; bf[2 * pp + 1][0] = r1;
                bf[2 * pp][1] = r2; bf[2 * pp + 1][1] = r3;
            }
#pragma unroll
            for (int mt = 0; mt < 4; mt++)
#pragma unroll
                for (int nt = 0; nt < 4; nt++)
                    mma_f16(c[mt][nt], af[mt][0], af[mt][1], af[mt][2], af[mt][3],
                            bf[nt][0], bf[nt][1]);
        }
        if (step + STAGES - 1 < 1024 / KC)
            issue_stage((step + STAGES - 1) & (STAGES - 1), (step + STAGES - 1) * KC);
        CP_COMMIT();
    }

    // NOTE: warp tile is 64 rows: mt covers wm + mt*16, mt=0..3 (64 rows).
    const float osc = p.scale[mat];
#pragma unroll
    for (int mt = 0; mt < 4; mt++) {
        const int r0 = m0 + wm + mt * 16 + (lane >> 2);
#pragma unroll
        for (int nt = 0; nt < 4; nt++) {
            const int nl = wn + nt * 8 + 2 * (lane & 3);
            const int n = n0l + nl;
            const float v0 = (c[mt][nt][0] + bsm[nl])     * osc;
            const float v1 = (c[mt][nt][1] + bsm[nl + 1]) * osc;
            const float v2 = (c[mt][nt][2] + bsm[nl])     * osc;
            const float v3 = (c[mt][nt][3] + bsm[nl + 1]) * osc;
            if (p.headmajor) {
                __half* O = (__half*)p.out[mat];
                const int h = n >> 6, hd = n & 63;
                const int b0_ = r0 >> 11, s0_ = r0 & (S - 1);
                const int b1_ = (r0 + 8) >> 11, s1_ = (r0 + 8) & (S - 1);
                *(__half2*)&O[((size_t)(b0_ * H + h) * S + s0_) * 64 + hd] =
                    __floats2half2_rn(v0, v1);
                *(__half2*)&O[((size_t)(b1_ * H + h) * S + s1_) * 64 + hd] =
                    __floats2half2_rn(v2, v3);
            } else {
                float* O = (float*)p.out[mat];
                *(float2*)&O[(size_t)r0 * 1024 + n]       = make_float2(v0, v1);
                *(float2*)&O[(size_t)(r0 + 8) * 1024 + n] = make_float2(v2, v3);
            }
        }
    }
}

// ---------------------------------------------------------------------------
// fp16 flash attention (exact R13): 128 q/CTA, 256 thr, 3-stage cp.async,
// ldmatrix, log2-domain max-free softmax, ones-column row sums.
// ---------------------------------------------------------------------------
constexpr int AST    = 3;
constexpr int APITCH = 72;
constexpr int TSTG   = 64 * APITCH;
constexpr int QROWS  = 128;
constexpr int ASMEM  = (QROWS * APITCH + 2 * AST * TSTG) * 2;   // 73728 B
constexpr uint32_t ONES_H2 = 0x3C003C00u;

__global__ __launch_bounds__(256, 2)
void attn_mma(const __half* __restrict__ Q, const __half* __restrict__ K,
              const __half* __restrict__ V, __half* __restrict__ Out)
{
    extern __shared__ __half asm_[];
    __half* Qs = asm_;
    __half* Ks = asm_ + QROWS * APITCH;
    __half* Vs = Ks + AST * TSTG;

    const int tid = threadIdx.x, lane = tid & 31, warp = tid >> 5;
    const int bh = blockIdx.y, q0 = blockIdx.x * QROWS;
    const __half* Qg = Q + ((size_t)bh * S + q0) * 64;
    const __half* Kg = K + (size_t)bh * S * 64;
    const __half* Vg = V + (size_t)bh * S * 64;

    const uint32_t qsb = smem_u32(Qs);
    const uint32_t ksb = smem_u32(Ks);
    const uint32_t vsb = smem_u32(Vs);

    const int krow = tid >> 2, kch = (tid & 3) * 16;
    auto issue_kv = [&](int stg, int kb) {
        const uint32_t kd = ksb + (stg * TSTG + krow * APITCH + kch) * 2;
        const __half* ks = &Kg[(size_t)(kb + krow) * 64 + kch];
        cp16(kd, ks);
        cp16(kd + 16, ks + 8);
        const uint32_t vd = vsb + (stg * TSTG + krow * APITCH + kch) * 2;
        const __half* vs = &Vg[(size_t)(kb + krow) * 64 + kch];
        cp16(vd, vs);
        cp16(vd + 16, vs + 8);
    };

    issue_kv(0, 0);  CP_COMMIT();
    issue_kv(1, 64); CP_COMMIT();

#pragma unroll
    for (int i = 0; i < 4; i++) {
        const int slot = tid + i * 256, row = slot >> 3, c8 = slot & 7;
        *(uint4*)&Qs[row * APITCH + c8 * 8] = *(const uint4*)&Qg[(size_t)row * 64 + c8 * 8];
    }
    __syncthreads();

    uint32_t qa[4][4];
#pragma unroll
    for (int kk = 0; kk < 4; kk++)
        ldsm4(qa[kk][0], qa[kk][1], qa[kk][2], qa[kk][3],
              qsb + ((warp * 16 + (lane & 15)) * APITCH + kk * 16 + (lane >> 4) * 8) * 2);

    uint32_t koffs[4];
#pragma unroll
    for (int g = 0; g < 4; g++)
        koffs[g] = (g * 16 + (lane & 15)) * APITCH + (lane >> 4) * 8;
    const int vrow_in = ((lane >> 3) & 1) * 8 + (lane & 7);
    const int vcol_in = (lane >> 4) * 8;

    float o[8][4];
#pragma unroll
    for (int dt = 0; dt < 8; dt++)
#pragma unroll
        for (int i = 0; i < 4; i++) o[dt][i] = 0.f;
    float ol[4] = {0.f, 0.f, 0.f, 0.f};

    int cur = 0;
    for (int kt = 0; kt < 32; kt++) {
        CP_WAIT1();
        __syncthreads();
        if (kt + 2 < 32) {
            int nst = cur + 2; if (nst >= AST) nst -= AST;
            issue_kv(nst, (kt + 2) * 64);
        }
        CP_COMMIT();

        const uint32_t kb = ksb + cur * TSTG * 2;
        const uint32_t vb = vsb + cur * TSTG * 2;

        float sc[8][4];
#pragma unroll
        for (int nt = 0; nt < 8; nt++)
#pragma unroll
            for (int i = 0; i < 4; i++) sc[nt][i] = 0.f;
#pragma unroll
        for (int kk = 0; kk < 4; kk++) {
            uint32_t bf[8][2];
#pragma unroll
            for (int g = 0; g < 4; g++) {
                uint32_t r0, r1, r2, r3;
                ldsm4(r0, r1, r2, r3, kb + (koffs[g] + kk * 16) * 2);
                bf[2 * g][0] = r0; bf[2 * g + 1][0] = r1;
                bf[2 * g][1] = r2; bf[2 * g + 1][1] = r3;
            }
#pragma unroll
            for (int nt = 0; nt < 8; nt++)
                mma_f16(sc[nt], qa[kk][0], qa[kk][1], qa[kk][2], qa[kk][3],
                        bf[nt][0], bf[nt][1]);
        }

        uint32_t ph[8][2];
#pragma unroll
        for (int nt = 0; nt < 8; nt++) {
            ph[nt][0] = h2exp2_u32(h2_as_u32(__floats2half2_rn(sc[nt][0], sc[nt][1])));
            ph[nt][1] = h2exp2_u32(h2_as_u32(__floats2half2_rn(sc[nt][2], sc[nt][3])));
        }

#pragma unroll
        for (int kk = 0; kk < 4; kk++) {
            uint32_t bv[8][2];
#pragma unroll
            for (int dg = 0; dg < 4; dg++) {
                uint32_t r0, r1, r2, r3;
                ldsm4t(r0, r1, r2, r3,
                       vb + ((kk * 16 + vrow_in) * APITCH + dg * 16 + vcol_in) * 2);
                bv[2 * dg][0] = r0; bv[2 * dg][1] = r1;
                bv[2 * dg + 1][0] = r2; bv[2 * dg + 1][1] = r3;
            }
#pragma unroll
            for (int dt = 0; dt < 8; dt++)
                mma_f16(o[dt], ph[2 * kk][0], ph[2 * kk][1],
                        ph[2 * kk + 1][0], ph[2 * kk + 1][1],
                        bv[dt][0], bv[dt][1]);
            mma_f16(ol, ph[2 * kk][0], ph[2 * kk][1],
                    ph[2 * kk + 1][0], ph[2 * kk + 1][1],
                    ONES_H2, ONES_H2);
        }

        if (++cur == AST) cur = 0;
    }

    const float i0 = 1.f / ol[0], i1 = 1.f / ol[2];
    const int b = bh >> 4, h = bh & 15;
    const int gr0 = q0 + warp * 16 + (lane >> 2);
    __half* Ob0 = Out + ((size_t)(b * S + gr0)) * 1024 + h * 64;
    __half* Ob1 = Ob0 + (size_t)8 * 1024;
#pragma unroll
    for (int dt = 0; dt < 8; dt++) {
        const int col = dt * 8 + 2 * (lane & 3);
        *(__half2*)&Ob0[col] = __floats2half2_rn(o[dt][0] * i0, o[dt][1] * i0);
        *(__half2*)&Ob1[col] = __floats2half2_rn(o[dt][2] * i1, o[dt][3] * i1);
    }
}

// ---------------------------------------------------------------------------
// Launch
// ---------------------------------------------------------------------------
extern "C" void kernel_launch(void* const* d_in, const int* in_sizes, int n_in,
                              void* d_out, int out_size)
{
    (void)in_sizes; (void)n_in; (void)out_size;

    const float* x  = (const float*)d_in[0];
    const float* Wq = (const float*)d_in[1];
    const float* bq = (const float*)d_in[2];
    const float* Wk = (const float*)d_in[3];
    const float* bk = (const float*)d_in[4];
    const float* Wv = (const float*)d_in[5];
    const float* bv = (const float*)d_in[6];
    const float* Wo = (const float*)d_in[7];
    const float* bo = (const float*)d_in[8];
    float* out = (float*)d_out;

    __half *xh, *wt, *qp, *kp, *vp, *ah;
    cudaGetSymbolAddress((void**)&xh, g_xh);
    cudaGetSymbolAddress((void**)&wt, g_wth);
    cudaGetSymbolAddress((void**)&qp, g_qh);
    cudaGetSymbolAddress((void**)&kp, g_kh);
    cudaGetSymbolAddress((void**)&vp, g_vh);
    cudaGetSymbolAddress((void**)&ah, g_ah);

    cudaFuncSetAttribute(gemm_big, cudaFuncAttributeMaxDynamicSharedMemorySize, GSMEM);
    cudaFuncSetAttribute(attn_mma, cudaFuncAttributeMaxDynamicSharedMemorySize, ASMEM);

    // Prep: x -> fp16, transpose+convert weights
    f2h_kernel<<<(M * D / 4 + 255) / 256, 256>>>(x, xh, M * D / 4);
    transpose_kernel<<<dim3(32, 32, 4), dim3(32, 8)>>>(Wq, Wk, Wv, Wo, wt);

    // Fused QKV projection. Q pre-scale folds 1/sqrt(HD) and log2(e).
    GemmP pq;
    pq.bias[0] = bq; pq.bias[1] = bk; pq.bias[2] = bv; pq.bias[3] = bo;
    pq.out[0] = qp;  pq.out[1] = kp;  pq.out[2] = vp;  pq.out[3] = nullptr;
    pq.scale[0] = 0.125f * 1.4426950408889634f;
    pq.scale[1] = 1.f; pq.scale[2] = 1.f; pq.scale[3] = 1.f;
    pq.headmajor = 1;
    gemm_big<<<dim3(24, M / 128), 256, GSMEM>>>(xh, wt, pq);

    // Attention: 128 queries per CTA
    attn_mma<<<dim3(S / QROWS, BH), 256, ASMEM>>>(qp, kp, vp, ah);

    // Output projection (fp32 out)
    GemmP po;
    po.bias[0] = bo; po.bias[1] = bo; po.bias[2] = bo; po.bias[3] = bo;
    po.out[0] = out; po.out[1] = out; po.out[2] = out; po.out[3] = out;
    po.scale[0] = 1.f; po.scale[1] = 1.f; po.scale[2] = 1.f; po.scale[3] = 1.f;
    po.headmajor = 0;
    gemm_big<<<dim3(8, M / 128), 256, GSMEM>>>(ah, wt + 3 * D * D, po);
}